// round 15
// baseline (speedup 1.0000x reference)
#include <cuda_runtime.h>
#include <cuda_fp16.h>
#include <cstdint>

// ============================================================================
// Problem constants
// ============================================================================
#define N_ROWS   65536
#define IN_DIM   256
#define OUT_DIM  256
#define NTYPES   8
#define BM       128                       // rows per block tile
#define BN       128                       // cols per block tile (OUT split in 2)
#define MAXTILES (N_ROWS / BM + NTYPES)    // 520 row-tiles
#define TOTALWORK (MAXTILES * 2)           // 1040 work items
#define NPERS    296                       // persistent CTAs (2 per SM x 148)
#define KC       64                        // K-chunk
#define NCHUNK   (IN_DIM / KC)             // 4
#define GTHREADS 256
#define SCAT_BLOCKS 64
#define WCONV_BLOCKS 512
#define XCONV_BLOCKS 4096

// SMEM layout (bytes) for GEMM:
//  [0]      s_idx[2][128]   1KB   (double-buffered across tiles)
//  [1024]   s_bias[2][128]  1KB
//  [2048]   3 stages x (Ah 16K | Bh 16K) = 96K
#define OFF_STAGE0  2048
#define STAGE_BYTES 32768
#define SMEM_BYTES  100352

// ============================================================================
// Device scratch
// ============================================================================
__device__ int g_cursor[NTYPES];   // reset by last scatter block each replay
__device__ int g_done;             // scatter completion counter (self-resetting)
__device__ int g_idx[MAXTILES * BM];
__device__ int g_meta[MAXTILES];   // per tile: type | (valid_count << 8), or -1
__device__ __align__(16) __half g_Wh[NTYPES * OUT_DIM * IN_DIM];
__device__ __align__(16) __half g_xh[N_ROWS * IN_DIM];          // 32 MB fp16 x

// ============================================================================
// Helpers
// ============================================================================
__device__ __forceinline__ uint32_t smem_u32(const void* p) {
    uint32_t a;
    asm("{ .reg .u64 t; cvta.to.shared.u64 t, %1; cvt.u32.u64 %0, t; }" : "=r"(a) : "l"(p));
    return a;
}

__device__ __forceinline__ uint32_t swz(uint32_t off) { return off ^ ((off >> 3) & 0x70); }

__device__ __forceinline__ void cpa16(uint32_t dst, const void* src) {
    asm volatile("cp.async.cg.shared.global [%0], [%1], 16;" :: "r"(dst), "l"(src));
}
__device__ __forceinline__ void cpa_commit() {
    asm volatile("cp.async.commit_group;");
}
template <int N> __device__ __forceinline__ void cpa_wait() {
    asm volatile("cp.async.wait_group %0;" :: "n"(N) : "memory");
}

__device__ __forceinline__ void ldsm4(uint32_t* r, uint32_t addr) {
    asm volatile("ldmatrix.sync.aligned.m8n8.x4.shared.b16 {%0,%1,%2,%3}, [%4];"
                 : "=r"(r[0]), "=r"(r[1]), "=r"(r[2]), "=r"(r[3]) : "r"(addr));
}

__device__ __forceinline__ void mma16816(float* c, const uint32_t* a, uint32_t b0, uint32_t b1) {
    asm volatile("mma.sync.aligned.m16n8k16.row.col.f32.f16.f16.f32 "
                 "{%0,%1,%2,%3}, {%4,%5,%6,%7}, {%8,%9}, {%0,%1,%2,%3};"
                 : "+f"(c[0]), "+f"(c[1]), "+f"(c[2]), "+f"(c[3])
                 : "r"(a[0]), "r"(a[1]), "r"(a[2]), "r"(a[3]), "r"(b0), "r"(b1));
}

__device__ __forceinline__ uint32_t h2_as_u32(__half2 h) {
    return *reinterpret_cast<uint32_t*>(&h);
}

__device__ __forceinline__ void stcs2(float* p, float2 v) {
    asm volatile("st.global.cs.v2.f32 [%0], {%1, %2};" :: "l"(p), "f"(v.x), "f"(v.y));
}

__device__ __forceinline__ uint2 cvt4(float4 v) {
    __half2 h01 = __floats2half2_rn(v.x, v.y);
    __half2 h23 = __floats2half2_rn(v.z, v.w);
    return make_uint2(h2_as_u32(h01), h2_as_u32(h23));
}

// evict-first fp32x4 load (stream-once data; keep L2 for g_xh/g_Wh)
__device__ __forceinline__ float4 ldcs4(const float* p) {
    float4 v;
    asm volatile("ld.global.cs.v4.f32 {%0,%1,%2,%3}, [%4];"
                 : "=f"(v.x), "=f"(v.y), "=f"(v.z), "=f"(v.w) : "l"(p));
    return v;
}

// ============================================================================
// k_prep: ONE kernel (unchanged from R14 — measured 14.9us, streaming-bound).
//   blocks [0,64): scatter (full local histogram -> identical padstart)
//   blocks [64,576): W fp32->fp16 | blocks [576,4672): x fp32->fp16
// ============================================================================
__global__ void __launch_bounds__(256) k_prep(const float* __restrict__ W,
                                              const float* __restrict__ x,
                                              const int* __restrict__ types) {
    const int bid = blockIdx.x, tid = threadIdx.x;

    if (bid < SCAT_BLOCKS) {
        __shared__ int h[NTYPES];
        __shared__ int c[NTYPES], base[NTYPES], padstart[NTYPES];
        if (tid < NTYPES) { h[tid] = 0; c[tid] = 0; }
        __syncthreads();

        const int4* t4 = (const int4*)types;            // 16384 int4 total
        #pragma unroll
        for (int batch = 0; batch < 2; ++batch) {
            unsigned long long pk = 0;
            #pragma unroll
            for (int r = 0; r < 32; ++r) {
                int4 tv = t4[(batch * 32 + r) * 256 + tid];
                pk += (1ULL << (8 * tv.x)) + (1ULL << (8 * tv.y))
                    + (1ULL << (8 * tv.z)) + (1ULL << (8 * tv.w));
            }
            #pragma unroll
            for (int t = 0; t < NTYPES; ++t)
                atomicAdd(&h[t], (int)((pk >> (8 * t)) & 0xFF));
        }
        __syncthreads();
        if (tid == 0) {
            int off = 0;
            for (int t = 0; t < NTYPES; t++) {
                padstart[t] = off;
                off += ((h[t] + BM - 1) / BM) * BM;
            }
        }
        __syncthreads();

        int i = bid * 256 + tid;
        int4 tv = t4[i];
        int p0 = atomicAdd(&c[tv.x], 1);
        int p1 = atomicAdd(&c[tv.y], 1);
        int p2 = atomicAdd(&c[tv.z], 1);
        int p3 = atomicAdd(&c[tv.w], 1);
        __syncthreads();
        if (tid < NTYPES) base[tid] = atomicAdd(&g_cursor[tid], c[tid]);
        __syncthreads();
        g_idx[padstart[tv.x] + base[tv.x] + p0] = i * 4;
        g_idx[padstart[tv.y] + base[tv.y] + p1] = i * 4 + 1;
        g_idx[padstart[tv.z] + base[tv.z] + p2] = i * 4 + 2;
        g_idx[padstart[tv.w] + base[tv.w] + p3] = i * 4 + 3;

        if (bid == 0) {
            for (int tile = tid; tile < MAXTILES; tile += 256) {
                int meta = -1;
                for (int t = 0; t < NTYPES; t++) {
                    int ts = padstart[t] / BM;
                    int tn = (h[t] + BM - 1) / BM;
                    if (tile >= ts && tile < ts + tn) {
                        int v = h[t] - (tile - ts) * BM;
                        if (v > BM) v = BM;
                        meta = t | (v << 8);
                    }
                }
                g_meta[tile] = meta;
            }
        }

        __syncthreads();
        __threadfence();
        if (tid == 0) {
            if (atomicAdd(&g_done, 1) == SCAT_BLOCKS - 1) {
                for (int t = 0; t < NTYPES; t++) g_cursor[t] = 0;
                g_done = 0;
            }
        }
        return;
    }

    if (bid < SCAT_BLOCKS + WCONV_BLOCKS) {
        int i4 = (bid - SCAT_BLOCKS) * 256 + tid;       // [0, 131072)
        float4 v = ldcs4(W + (size_t)i4 * 4);
        *(uint2*)(g_Wh + (size_t)i4 * 4) = cvt4(v);
        return;
    }
    int base4 = (bid - SCAT_BLOCKS - WCONV_BLOCKS) * 1024 + tid;
    #pragma unroll
    for (int r = 0; r < 4; ++r) {
        int i4 = base4 + r * 256;                       // [0, 4194304)
        float4 v = ldcs4(x + (size_t)i4 * 4);
        *(uint2*)(g_xh + (size_t)i4 * 4) = cvt4(v);
    }
}

// ============================================================================
// Persistent grouped GEMM: NPERS CTAs, flat cross-tile chunk pipeline.
// Work item w = (tile, nside): D[128,128] = gather(xh) * Wh^T + bias.
// Pure cp.async + ldmatrix + mma; 3 smem stages; pipeline NEVER drains
// between tiles (next tile's chunks 0..1 issued during current tile's 2..3;
// next tile's s_idx/bias prefetched one tile ahead into a double buffer).
// 8 warps in 2(M)x4(N); warp tile 64x32; 64 fp32 acc/thread; 2 CTAs/SM.
// ============================================================================
__global__ void __launch_bounds__(GTHREADS, 2)
typed_linear_gemm(const float* __restrict__ bias, float* __restrict__ out) {
    extern __shared__ char smem[];
    const int tid  = threadIdx.x;
    const int wid  = tid >> 5;
    const int lane = tid & 31;
    const uint32_t sb = smem_u32(smem);

    int*   s_idx  = (int*)smem;            // [2][128]
    float* s_bias = (float*)(smem + 1024); // [2][128]

    // ---- decode + tile-buffer loader ----
    auto load_tile = [&](int w, int p, int& t_out, int& ns_out) {
        int tile = w >> 1, ns = w & 1;
        int meta = g_meta[tile];
        int t  = (meta < 0) ? 0 : (meta & 0xFF);
        int vc = (meta < 0) ? 0 : (meta >> 8);
        if (tid < BM) s_idx[p * 128 + tid] = (tid < vc) ? g_idx[tile * BM + tid] : -1;
        if (tid < BN) s_bias[p * 128 + tid] = bias[t * OUT_DIM + ns * BN + tid];
        t_out = t; ns_out = ns;
    };

    auto issue_chunk = [&](int stage, int kb, const int* sidx, const __half* Wt) {
        const uint32_t stg = sb + OFF_STAGE0 + (uint32_t)stage * STAGE_BYTES;
        #pragma unroll
        for (int r = 0; r < 4; ++r) {
            int i16 = r * GTHREADS + tid;          // [0,1024)
            int m = i16 >> 3, k16 = i16 & 7;
            int g = sidx[m];
            uint32_t d = swz((uint32_t)(m * 128 + k16 * 16));
            cpa16(stg + d, g_xh + (size_t)(g < 0 ? 0 : g) * IN_DIM + kb + k16 * 8);
        }
        #pragma unroll
        for (int r = 0; r < 4; ++r) {
            int i16 = r * GTHREADS + tid;          // [0,1024)
            int n = i16 >> 3, k16 = i16 & 7;
            uint32_t d = swz((uint32_t)(n * 128 + k16 * 16));
            cpa16(stg + 16384u + d, Wt + (size_t)n * IN_DIM + kb + k16 * 8);
        }
        cpa_commit();
    };

    // -------- warp/lane constants for ldmatrix (stage-relative) --------
    const int mgrp = wid >> 2;      // rows [64*mgrp, +64)
    const int nq   = wid & 3;       // cols [32*nq, +32) within the 128-col tile
    const int j = lane & 7, sub = lane >> 3;

    uint32_t a_base[4], a_xr[4], b_base[2], b_xr[2];
    #pragma unroll
    for (int mt = 0; mt < 4; ++mt) {
        int row = mgrp * 64 + mt * 16 + j + (sub & 1) * 8;
        a_xr[mt]   = (uint32_t)((row & 7) * 16);
        a_base[mt] = (uint32_t)(row * 128) + (uint32_t)((sub >> 1) * 16);
    }
    #pragma unroll
    for (int nt = 0; nt < 2; ++nt) {
        int row = nq * 32 + nt * 16 + (sub >> 1) * 8 + j;
        b_xr[nt]   = (uint32_t)((row & 7) * 16);
        b_base[nt] = (uint32_t)(row * 128) + (uint32_t)((sub & 1) * 16);
    }

    // ---- prologue: first work item ----
    int w = blockIdx.x;
    int p = 0;                         // current s_idx/bias buffer
    int tcur, nscur;
    load_tile(w, 0, tcur, nscur);
    __syncthreads();
    const __half* Wcur = g_Wh + ((size_t)tcur * OUT_DIM + nscur * BN) * IN_DIM;

    issue_chunk(0, 0,  s_idx, Wcur);
    issue_chunk(1, KC, s_idx, Wcur);
    int stage_cur = 0, stage_nxt = 2;  // mod-3 stage cursors (compute / issue)

    float acc[4][4][4];
    #pragma unroll
    for (int mt = 0; mt < 4; ++mt)
        #pragma unroll
        for (int i = 0; i < 4; ++i)
            #pragma unroll
            for (int q = 0; q < 4; ++q) acc[mt][i][q] = 0.f;

    for (;;) {
        const int wn = w + NPERS;
        const bool have_next = (wn < TOTALWORK);
        int tnext = 0, nsnext = 0;
        const __half* Wnext = g_Wh;
        if (have_next) {
            load_tile(wn, p ^ 1, tnext, nsnext);   // published by chunk-0 sync
            Wnext = g_Wh + ((size_t)tnext * OUT_DIM + nsnext * BN) * IN_DIM;
        }
        const int* sidx_cur = s_idx + p * 128;
        const int* sidx_nxt = s_idx + (p ^ 1) * 128;

        #pragma unroll
        for (int c = 0; c < NCHUNK; ++c) {
            if (c == NCHUNK - 1 && !have_next) cpa_wait<0>(); else cpa_wait<1>();
            __syncthreads();           // chunk c arrived; stage_nxt's old data consumed

            if (c < 2) {
                issue_chunk(stage_nxt, (c + 2) * KC, sidx_cur, Wcur);
                stage_nxt = (stage_nxt == 2) ? 0 : stage_nxt + 1;
            } else if (have_next) {
                issue_chunk(stage_nxt, (c - 2) * KC, sidx_nxt, Wnext);
                stage_nxt = (stage_nxt == 2) ? 0 : stage_nxt + 1;
            }

            // ---- compute chunk c ----
            const uint32_t stg = sb + OFF_STAGE0 + (uint32_t)stage_cur * STAGE_BYTES;
            const uint32_t Ah = stg, Bh = stg + 16384u;
            #pragma unroll
            for (int ks = 0; ks < 4; ++ks) {
                const uint32_t kb = (uint32_t)(ks * 32);
                uint32_t ah[4][4], bhr[2][4];
                #pragma unroll
                for (int mt = 0; mt < 4; ++mt)
                    ldsm4(ah[mt], Ah + ((a_base[mt] + kb) ^ a_xr[mt]));
                #pragma unroll
                for (int nt = 0; nt < 2; ++nt)
                    ldsm4(bhr[nt], Bh + ((b_base[nt] + kb) ^ b_xr[nt]));
                #pragma unroll
                for (int nt = 0; nt < 2; ++nt)
                    #pragma unroll
                    for (int mt = 0; mt < 4; ++mt) {
                        mma16816(acc[mt][2 * nt],     ah[mt], bhr[nt][0], bhr[nt][1]);
                        mma16816(acc[mt][2 * nt + 1], ah[mt], bhr[nt][2], bhr[nt][3]);
                    }
            }
            stage_cur = (stage_cur == 2) ? 0 : stage_cur + 1;
        }

        // ---- epilogue for tile w (overlaps next tile's in-flight cp.async) ----
        const float* bcur = s_bias + p * 128;
        #pragma unroll
        for (int mt = 0; mt < 4; ++mt) {
            const int r0 = mgrp * 64 + mt * 16 + (lane >> 2);
            const int g0 = sidx_cur[r0];
            const int g1 = sidx_cur[r0 + 8];
            #pragma unroll
            for (int n8 = 0; n8 < 4; ++n8) {
                const int lcol = nq * 32 + n8 * 8 + (lane & 3) * 2;
                const int col  = nscur * BN + lcol;
                const float bv0 = bcur[lcol], bv1 = bcur[lcol + 1];
                if (g0 >= 0)
                    stcs2(out + (size_t)g0 * OUT_DIM + col,
                          make_float2(acc[mt][n8][0] + bv0, acc[mt][n8][1] + bv1));
                if (g1 >= 0)
                    stcs2(out + (size_t)g1 * OUT_DIM + col,
                          make_float2(acc[mt][n8][2] + bv0, acc[mt][n8][3] + bv1));
            }
        }

        if (!have_next) break;
        __syncthreads();               // epilogue done before buffer p is rewritten

        w = wn; p ^= 1; tcur = tnext; nscur = nsnext; Wcur = Wnext;
        #pragma unroll
        for (int mt = 0; mt < 4; ++mt)
            #pragma unroll
            for (int i = 0; i < 4; ++i)
                #pragma unroll
                for (int q = 0; q < 4; ++q) acc[mt][i][q] = 0.f;
    }
}

// ============================================================================
// Launch (2 kernels total)
// ============================================================================
extern "C" void kernel_launch(void* const* d_in, const int* in_sizes, int n_in,
                              void* d_out, int out_size) {
    const float* x     = (const float*)d_in[0];
    const int*   types = (const int*)d_in[1];
    const float* W     = (const float*)d_in[2];
    const float* b     = (const float*)d_in[3];
    float*       out   = (float*)d_out;

    cudaFuncSetAttribute(typed_linear_gemm, cudaFuncAttributeMaxDynamicSharedMemorySize,
                         SMEM_BYTES);

    k_prep<<<SCAT_BLOCKS + WCONV_BLOCKS + XCONV_BLOCKS, 256>>>(W, x, types);
    typed_linear_gemm<<<NPERS, GTHREADS, SMEM_BYTES>>>(b, out);
}

// round 16
// speedup vs baseline: 1.0833x; 1.0833x over previous
#include <cuda_runtime.h>
#include <cuda_fp16.h>
#include <cstdint>

// ============================================================================
// Problem constants
// ============================================================================
#define N_ROWS   65536
#define IN_DIM   256
#define OUT_DIM  256
#define NTYPES   8
#define BM       128                       // rows per block tile
#define BN       128                       // cols per block tile (OUT split in 2)
#define MAXTILES (N_ROWS / BM + NTYPES)    // 520 row-tiles
#define KC       64                        // K-chunk
#define NCHUNK   (IN_DIM / KC)             // 4
#define GTHREADS 256
#define SCAT_BLOCKS 64
#define WCONV_BLOCKS 512
#define XCONV_BLOCKS 4096

// SMEM layout (bytes) for GEMM:
//  [0]      s_idx[128]     512B
//  [512]    s_bias[128]    512B
//  [1024]   3 stages x (Ah 16K | Bh 16K) = 96K
#define OFF_STAGE0  1024
#define STAGE_BYTES 32768
#define SMEM_BYTES  99328

// ============================================================================
// Device scratch
// ============================================================================
__device__ int g_cursor[NTYPES];   // reset by last scatter block each replay
__device__ int g_done;             // scatter completion counter (self-resetting)
__device__ int g_idx[MAXTILES * BM];
__device__ int g_meta[MAXTILES];   // per tile: type | (valid_count << 8), or -1
__device__ __align__(16) __half g_Wh[NTYPES * OUT_DIM * IN_DIM];
__device__ __align__(16) __half g_xh[N_ROWS * IN_DIM];          // 32 MB fp16 x

// ============================================================================
// Helpers
// ============================================================================
__device__ __forceinline__ uint32_t smem_u32(const void* p) {
    uint32_t a;
    asm("{ .reg .u64 t; cvta.to.shared.u64 t, %1; cvt.u32.u64 %0, t; }" : "=r"(a) : "l"(p));
    return a;
}

__device__ __forceinline__ uint32_t swz(uint32_t off) { return off ^ ((off >> 3) & 0x70); }

__device__ __forceinline__ void cpa16(uint32_t dst, const void* src) {
    asm volatile("cp.async.cg.shared.global [%0], [%1], 16;" :: "r"(dst), "l"(src));
}
__device__ __forceinline__ void cpa_commit() {
    asm volatile("cp.async.commit_group;");
}
template <int N> __device__ __forceinline__ void cpa_wait() {
    asm volatile("cp.async.wait_group %0;" :: "n"(N) : "memory");
}

__device__ __forceinline__ void ldsm4(uint32_t* r, uint32_t addr) {
    asm volatile("ldmatrix.sync.aligned.m8n8.x4.shared.b16 {%0,%1,%2,%3}, [%4];"
                 : "=r"(r[0]), "=r"(r[1]), "=r"(r[2]), "=r"(r[3]) : "r"(addr));
}

__device__ __forceinline__ void mma16816(float* c, const uint32_t* a, uint32_t b0, uint32_t b1) {
    asm volatile("mma.sync.aligned.m16n8k16.row.col.f32.f16.f16.f32 "
                 "{%0,%1,%2,%3}, {%4,%5,%6,%7}, {%8,%9}, {%0,%1,%2,%3};"
                 : "+f"(c[0]), "+f"(c[1]), "+f"(c[2]), "+f"(c[3])
                 : "r"(a[0]), "r"(a[1]), "r"(a[2]), "r"(a[3]), "r"(b0), "r"(b1));
}

__device__ __forceinline__ uint32_t h2_as_u32(__half2 h) {
    return *reinterpret_cast<uint32_t*>(&h);
}

__device__ __forceinline__ void stcs2(float* p, float2 v) {
    asm volatile("st.global.cs.v2.f32 [%0], {%1, %2};" :: "l"(p), "f"(v.x), "f"(v.y));
}

__device__ __forceinline__ uint2 cvt4(float4 v) {
    __half2 h01 = __floats2half2_rn(v.x, v.y);
    __half2 h23 = __floats2half2_rn(v.z, v.w);
    return make_uint2(h2_as_u32(h01), h2_as_u32(h23));
}

// evict-first fp32x4 load (stream-once data; keep L2 for g_xh/g_Wh)
__device__ __forceinline__ float4 ldcs4(const float* p) {
    float4 v;
    asm volatile("ld.global.cs.v4.f32 {%0,%1,%2,%3}, [%4];"
                 : "=f"(v.x), "=f"(v.y), "=f"(v.z), "=f"(v.w) : "l"(p));
    return v;
}

// ============================================================================
// k_prep: ONE kernel (R14-proven, streaming-bound at ~15us).
//   blocks [0,64): scatter (full local histogram -> identical padstart)
//   blocks [64,576): W fp32->fp16 | blocks [576,4672): x fp32->fp16
// ============================================================================
__global__ void __launch_bounds__(256) k_prep(const float* __restrict__ W,
                                              const float* __restrict__ x,
                                              const int* __restrict__ types) {
    const int bid = blockIdx.x, tid = threadIdx.x;

    if (bid < SCAT_BLOCKS) {
        __shared__ int h[NTYPES];
        __shared__ int c[NTYPES], base[NTYPES], padstart[NTYPES];
        if (tid < NTYPES) { h[tid] = 0; c[tid] = 0; }
        __syncthreads();

        const int4* t4 = (const int4*)types;            // 16384 int4 total
        #pragma unroll
        for (int batch = 0; batch < 2; ++batch) {
            unsigned long long pk = 0;
            #pragma unroll
            for (int r = 0; r < 32; ++r) {
                int4 tv = t4[(batch * 32 + r) * 256 + tid];
                pk += (1ULL << (8 * tv.x)) + (1ULL << (8 * tv.y))
                    + (1ULL << (8 * tv.z)) + (1ULL << (8 * tv.w));
            }
            #pragma unroll
            for (int t = 0; t < NTYPES; ++t)
                atomicAdd(&h[t], (int)((pk >> (8 * t)) & 0xFF));
        }
        __syncthreads();
        if (tid == 0) {
            int off = 0;
            for (int t = 0; t < NTYPES; t++) {
                padstart[t] = off;
                off += ((h[t] + BM - 1) / BM) * BM;
            }
        }
        __syncthreads();

        int i = bid * 256 + tid;
        int4 tv = t4[i];
        int p0 = atomicAdd(&c[tv.x], 1);
        int p1 = atomicAdd(&c[tv.y], 1);
        int p2 = atomicAdd(&c[tv.z], 1);
        int p3 = atomicAdd(&c[tv.w], 1);
        __syncthreads();
        if (tid < NTYPES) base[tid] = atomicAdd(&g_cursor[tid], c[tid]);
        __syncthreads();
        g_idx[padstart[tv.x] + base[tv.x] + p0] = i * 4;
        g_idx[padstart[tv.y] + base[tv.y] + p1] = i * 4 + 1;
        g_idx[padstart[tv.z] + base[tv.z] + p2] = i * 4 + 2;
        g_idx[padstart[tv.w] + base[tv.w] + p3] = i * 4 + 3;

        if (bid == 0) {
            for (int tile = tid; tile < MAXTILES; tile += 256) {
                int meta = -1;
                for (int t = 0; t < NTYPES; t++) {
                    int ts = padstart[t] / BM;
                    int tn = (h[t] + BM - 1) / BM;
                    if (tile >= ts && tile < ts + tn) {
                        int v = h[t] - (tile - ts) * BM;
                        if (v > BM) v = BM;
                        meta = t | (v << 8);
                    }
                }
                g_meta[tile] = meta;
            }
        }

        __syncthreads();
        __threadfence();
        if (tid == 0) {
            if (atomicAdd(&g_done, 1) == SCAT_BLOCKS - 1) {
                for (int t = 0; t < NTYPES; t++) g_cursor[t] = 0;
                g_done = 0;
            }
        }
        return;
    }

    if (bid < SCAT_BLOCKS + WCONV_BLOCKS) {
        int i4 = (bid - SCAT_BLOCKS) * 256 + tid;       // [0, 131072)
        float4 v = ldcs4(W + (size_t)i4 * 4);
        *(uint2*)(g_Wh + (size_t)i4 * 4) = cvt4(v);
        return;
    }
    int base4 = (bid - SCAT_BLOCKS - WCONV_BLOCKS) * 1024 + tid;
    #pragma unroll
    for (int r = 0; r < 4; ++r) {
        int i4 = base4 + r * 256;                       // [0, 4194304)
        float4 v = ldcs4(x + (size_t)i4 * 4);
        *(uint2*)(g_xh + (size_t)i4 * 4) = cvt4(v);
    }
}

// ============================================================================
// Grouped GEMM (R14 core): block = (row-tile, N-half).
// D[128,128] = gather(xh)*Wh^T + b. Pure cp.async + ldmatrix + mma;
// 3-stage pipeline, prefetch depth 2. Prologue overlap: B(0),B(1) issued
// while the s_idx/bias LDGs are in flight (B doesn't depend on s_idx),
// then A(0),A(1) after the barrier. Wait schedule: group order
// B0,B1,A0,A1,AB2,AB3 -> wait<1> per chunk gives exactly {A(c),B(c)} ready.
// 8 warps in 2(M)x4(N); warp tile 64x32; 64 fp32 acc/thread; 2 CTAs/SM.
// ============================================================================
__global__ void __launch_bounds__(GTHREADS, 2)
typed_linear_gemm(const float* __restrict__ b, float* __restrict__ out) {
    extern __shared__ char smem[];
    const int tile  = blockIdx.x >> 1;
    const int nside = blockIdx.x & 1;
    const int meta = g_meta[tile];
    if (meta < 0) return;
    const int t    = meta & 0xFF;
    const int vcnt = meta >> 8;

    const int tid  = threadIdx.x;
    const int wid  = tid >> 5;
    const int lane = tid & 31;
    const uint32_t sb = smem_u32(smem);

    int*   s_idx  = (int*)smem;
    float* s_bias = (float*)(smem + 512);

    const __half* Wh_t = g_Wh + ((size_t)t * OUT_DIM + nside * BN) * IN_DIM;

    // ---- kick the idx/bias LDGs (results consumed after B-issues below) ----
    int   idxv = -1;
    float bv   = 0.f;
    if (tid < BM) idxv = (tid < vcnt) ? g_idx[tile * BM + tid] : -1;
    if (tid < BN) bv = b[t * OUT_DIM + nside * BN + tid];

    auto issueB = [&](int c) {
        const int kb = c * KC;
        const uint32_t stg = sb + OFF_STAGE0 + (uint32_t)(c % 3) * STAGE_BYTES;
        #pragma unroll
        for (int r = 0; r < 4; ++r) {
            int i16 = r * GTHREADS + tid;          // [0,1024)
            int n = i16 >> 3, k16 = i16 & 7;
            uint32_t d = swz((uint32_t)(n * 128 + k16 * 16));
            cpa16(stg + 16384u + d, Wh_t + (size_t)n * IN_DIM + kb + k16 * 8);
        }
        cpa_commit();
    };
    auto issueA = [&](int c) {
        const int kb = c * KC;
        const uint32_t stg = sb + OFF_STAGE0 + (uint32_t)(c % 3) * STAGE_BYTES;
        #pragma unroll
        for (int r = 0; r < 4; ++r) {
            int i16 = r * GTHREADS + tid;          // [0,1024)
            int m = i16 >> 3, k16 = i16 & 7;
            int g = s_idx[m];
            uint32_t d = swz((uint32_t)(m * 128 + k16 * 16));
            cpa16(stg + d, g_xh + (size_t)(g < 0 ? 0 : g) * IN_DIM + kb + k16 * 8);
        }
        cpa_commit();
    };
    auto issueAB = [&](int c) {
        const int kb = c * KC;
        const uint32_t stg = sb + OFF_STAGE0 + (uint32_t)(c % 3) * STAGE_BYTES;
        #pragma unroll
        for (int r = 0; r < 4; ++r) {
            int i16 = r * GTHREADS + tid;
            int m = i16 >> 3, k16 = i16 & 7;
            int g = s_idx[m];
            uint32_t d = swz((uint32_t)(m * 128 + k16 * 16));
            cpa16(stg + d, g_xh + (size_t)(g < 0 ? 0 : g) * IN_DIM + kb + k16 * 8);
        }
        #pragma unroll
        for (int r = 0; r < 4; ++r) {
            int i16 = r * GTHREADS + tid;
            int n = i16 >> 3, k16 = i16 & 7;
            uint32_t d = swz((uint32_t)(n * 128 + k16 * 16));
            cpa16(stg + 16384u + d, Wh_t + (size_t)n * IN_DIM + kb + k16 * 8);
        }
        cpa_commit();
    };

    // B(0), B(1) overlap the idx/bias LDG latency
    issueB(0);
    issueB(1);

    if (tid < BM) s_idx[tid] = idxv;       // STS waits on the LDG here
    if (tid < BN) s_bias[tid] = bv;
    __syncthreads();

    issueA(0);
    issueA(1);

    // -------- warp/lane constants for ldmatrix --------
    const int mgrp = wid >> 2;      // rows [64*mgrp, +64)
    const int nq   = wid & 3;       // cols [32*nq, +32) within the 128-col tile
    const int j = lane & 7, sub = lane >> 3;

    uint32_t a_base[4], a_xr[4], b_base[2], b_xr[2];
    #pragma unroll
    for (int mt = 0; mt < 4; ++mt) {
        int row = mgrp * 64 + mt * 16 + j + (sub & 1) * 8;
        a_xr[mt]   = (uint32_t)((row & 7) * 16);
        a_base[mt] = (uint32_t)(row * 128) + (uint32_t)((sub >> 1) * 16);
    }
    #pragma unroll
    for (int nt = 0; nt < 2; ++nt) {
        int row = nq * 32 + nt * 16 + (sub >> 1) * 8 + j;
        b_xr[nt]   = (uint32_t)((row & 7) * 16);
        b_base[nt] = (uint32_t)(row * 128) + (uint32_t)((sub & 1) * 16);
    }

    float acc[4][4][4];   // [mt][n8][quad]
    #pragma unroll
    for (int mt = 0; mt < 4; ++mt)
        #pragma unroll
        for (int i = 0; i < 4; ++i)
            #pragma unroll
            for (int q = 0; q < 4; ++q) acc[mt][i][q] = 0.f;

    #pragma unroll
    for (int c = 0; c < NCHUNK; ++c) {
        const uint32_t stg = sb + OFF_STAGE0 + (uint32_t)(c % 3) * STAGE_BYTES;
        const uint32_t Ah = stg, Bh = stg + 16384u;

        // group order: B0,B1,A0,A1,AB2,AB3.
        // c=0: wait<1> -> B0,B1,A0 done (A1 pending)        : need A0,B0 ok
        // c=1: wait<1> -> ...A1 done (AB2 pending)          : need A1,B1 ok
        // c=2: wait<1> -> AB2 done (AB3 pending)            : ok
        // c=3: wait<0> -> all done                          : ok
        if (c == NCHUNK - 1) cpa_wait<0>(); else cpa_wait<1>();
        __syncthreads();   // all warps past compute(c-1); stage (c+2)%3 free

        if (c + 2 < NCHUNK) issueAB(c + 2);

        // ---- compute chunk c: 4 K16 steps ----
        #pragma unroll
        for (int ks = 0; ks < 4; ++ks) {
            const uint32_t kb = (uint32_t)(ks * 32);
            uint32_t ah[4][4], bhr[2][4];
            #pragma unroll
            for (int mt = 0; mt < 4; ++mt)
                ldsm4(ah[mt], Ah + ((a_base[mt] + kb) ^ a_xr[mt]));
            #pragma unroll
            for (int nt = 0; nt < 2; ++nt)
                ldsm4(bhr[nt], Bh + ((b_base[nt] + kb) ^ b_xr[nt]));
            #pragma unroll
            for (int nt = 0; nt < 2; ++nt)
                #pragma unroll
                for (int mt = 0; mt < 4; ++mt) {
                    mma16816(acc[mt][2 * nt],     ah[mt], bhr[nt][0], bhr[nt][1]);
                    mma16816(acc[mt][2 * nt + 1], ah[mt], bhr[nt][2], bhr[nt][3]);
                }
        }
    }

    // ---- epilogue: bias + scatter-store (streaming) ----
    #pragma unroll
    for (int mt = 0; mt < 4; ++mt) {
        const int r0 = mgrp * 64 + mt * 16 + (lane >> 2);
        const int g0 = s_idx[r0];
        const int g1 = s_idx[r0 + 8];
        #pragma unroll
        for (int n8 = 0; n8 < 4; ++n8) {
            const int lcol = nq * 32 + n8 * 8 + (lane & 3) * 2;
            const int col  = nside * BN + lcol;
            const float bv0 = s_bias[lcol], bv1 = s_bias[lcol + 1];
            if (g0 >= 0)
                stcs2(out + (size_t)g0 * OUT_DIM + col,
                      make_float2(acc[mt][n8][0] + bv0, acc[mt][n8][1] + bv1));
            if (g1 >= 0)
                stcs2(out + (size_t)g1 * OUT_DIM + col,
                      make_float2(acc[mt][n8][2] + bv0, acc[mt][n8][3] + bv1));
        }
    }
}

// ============================================================================
// Launch (2 kernels total)
// ============================================================================
extern "C" void kernel_launch(void* const* d_in, const int* in_sizes, int n_in,
                              void* d_out, int out_size) {
    const float* x     = (const float*)d_in[0];
    const int*   types = (const int*)d_in[1];
    const float* W     = (const float*)d_in[2];
    const float* b     = (const float*)d_in[3];
    float*       out   = (float*)d_out;

    cudaFuncSetAttribute(typed_linear_gemm, cudaFuncAttributeMaxDynamicSharedMemorySize,
                         SMEM_BYTES);

    k_prep<<<SCAT_BLOCKS + WCONV_BLOCKS + XCONV_BLOCKS, 256>>>(W, x, types);
    typed_linear_gemm<<<MAXTILES * 2, GTHREADS, SMEM_BYTES>>>(b, out);
}